// round 1
// baseline (speedup 1.0000x reference)
#include <cuda_runtime.h>
#include <cstdint>
#include <cstddef>

namespace {

constexpr int B_ = 8;
constexpr int K_ = 9;
constexpr int N_ = 1024;
constexpr int D_ = 64;

constexpr int TILE_N = 32;   // output rows per block
constexpr int TM     = 32;   // m-tile width
constexpr int NWARP  = 2;    // warps per block; warps split the m-range
constexpr int WSP    = TM + 4;  // padded ws row stride (36 floats -> bank shift of 4)

// coefficients (1-eps)^k, eps = 0.01
#define C1 0.99f
#define C2 0.9801f
#define C3 0.970299f
#define C4 0.96059601f
#define C5 0.9509900499f
#define C6 0.941480149401f
#define C7 0.93206534790699f
#define C8 0.9227446944279201f
constexpr float INV_S = 1.0f / 8.648275251635911f;  // 1 / sum_k (0.99)^k

__device__ __forceinline__ unsigned long long pack2(float a) {
    unsigned long long r;
    unsigned int u = __float_as_uint(a);
    asm("mov.b64 %0, {%1, %1};" : "=l"(r) : "r"(u));
    return r;
}
__device__ __forceinline__ void fma2(unsigned long long& d, unsigned long long a,
                                     unsigned long long b) {
    asm("fma.rn.f32x2 %0, %1, %2, %0;" : "+l"(d) : "l"(a), "l"(b));
}
__device__ __forceinline__ float2 unpack2(unsigned long long v) {
    unsigned int lo, hi;
    asm("mov.b64 {%0, %1}, %2;" : "=r"(lo), "=r"(hi) : "l"(v));
    return make_float2(__uint_as_float(lo), __uint_as_float(hi));
}

__global__ __launch_bounds__(NWARP * 32, 6)
void fused_gpe_kernel(const float* __restrict__ x,
                      const float* __restrict__ gr,
                      float* __restrict__ out) {
    __shared__ float xs[NWARP][TM * D_];        // 2 x 8 KB  (x tiles; reused as partial-acc buf)
    __shared__ float ws[NWARP][TILE_N * WSP];   // 2 x 4.5 KB (weighted kernel tiles)

    const int b    = blockIdx.y;
    const int n0   = blockIdx.x * TILE_N;
    const int warp = threadIdx.x >> 5;
    const int lane = threadIdx.x & 31;
    const int rg   = lane >> 3;   // 0..3  row group  (rows n = rg + 4*r)
    const int cg   = lane & 7;    // 0..7  col group  (cols cg*4..+3 and cg*4+32..+3)

    const float* xb  = x  + (size_t)b * N_ * D_;
    const float* grb = gr + (size_t)b * K_ * N_ * N_;

    // 8 rows x 8 cols of fp32 accumulators, held as f32x2 pairs
    unsigned long long acc[8][4];
#pragma unroll
    for (int r = 0; r < 8; ++r)
#pragma unroll
        for (int i = 0; i < 4; ++i) acc[r][i] = 0ull;

    for (int tile = warp; tile < N_ / TM; tile += NWARP) {
        const int m0 = tile * TM;

        // ---- stage x[m0:m0+32, 0:64] into smem (2048 floats / warp) ----
#pragma unroll
        for (int i = 0; i < 16; ++i) {
            int f4 = lane + 32 * i;            // 0..511 float4 index
            int m  = f4 >> 4, d4 = f4 & 15;
            *reinterpret_cast<float4*>(&xs[warp][m * D_ + d4 * 4]) =
                *reinterpret_cast<const float4*>(xb + (size_t)(m0 + m) * D_ + d4 * 4);
        }

        // ---- weighted k-sum: ws[n][m] = sum_k c_k * gr[b,k,n0+n,m0+m] ----
        // 9 independent LDG.128 per step; immediate-coefficient FFMA (rt=1)
#pragma unroll 1
        for (int j = 0; j < 8; ++j) {
            int f4 = lane + 32 * j;            // 0..255
            int nn = f4 >> 3, m4 = f4 & 7;
            const float* g = grb + (size_t)(n0 + nn) * N_ + (m0 + m4 * 4);
            const size_t ks = (size_t)N_ * N_;
            float4 g0 = *reinterpret_cast<const float4*>(g);
            float4 g1 = *reinterpret_cast<const float4*>(g + ks);
            float4 g2 = *reinterpret_cast<const float4*>(g + 2 * ks);
            float4 g3 = *reinterpret_cast<const float4*>(g + 3 * ks);
            float4 g4 = *reinterpret_cast<const float4*>(g + 4 * ks);
            float4 g5 = *reinterpret_cast<const float4*>(g + 5 * ks);
            float4 g6 = *reinterpret_cast<const float4*>(g + 6 * ks);
            float4 g7 = *reinterpret_cast<const float4*>(g + 7 * ks);
            float4 g8 = *reinterpret_cast<const float4*>(g + 8 * ks);
            float4 w;
            w.x = g0.x; w.y = g0.y; w.z = g0.z; w.w = g0.w;
            w.x = fmaf(g1.x, C1, w.x); w.y = fmaf(g1.y, C1, w.y); w.z = fmaf(g1.z, C1, w.z); w.w = fmaf(g1.w, C1, w.w);
            w.x = fmaf(g2.x, C2, w.x); w.y = fmaf(g2.y, C2, w.y); w.z = fmaf(g2.z, C2, w.z); w.w = fmaf(g2.w, C2, w.w);
            w.x = fmaf(g3.x, C3, w.x); w.y = fmaf(g3.y, C3, w.y); w.z = fmaf(g3.z, C3, w.z); w.w = fmaf(g3.w, C3, w.w);
            w.x = fmaf(g4.x, C4, w.x); w.y = fmaf(g4.y, C4, w.y); w.z = fmaf(g4.z, C4, w.z); w.w = fmaf(g4.w, C4, w.w);
            w.x = fmaf(g5.x, C5, w.x); w.y = fmaf(g5.y, C5, w.y); w.z = fmaf(g5.z, C5, w.z); w.w = fmaf(g5.w, C5, w.w);
            w.x = fmaf(g6.x, C6, w.x); w.y = fmaf(g6.y, C6, w.y); w.z = fmaf(g6.z, C6, w.z); w.w = fmaf(g6.w, C6, w.w);
            w.x = fmaf(g7.x, C7, w.x); w.y = fmaf(g7.y, C7, w.y); w.z = fmaf(g7.z, C7, w.z); w.w = fmaf(g7.w, C7, w.w);
            w.x = fmaf(g8.x, C8, w.x); w.y = fmaf(g8.y, C8, w.y); w.z = fmaf(g8.z, C8, w.z); w.w = fmaf(g8.w, C8, w.w);
            *reinterpret_cast<float4*>(&ws[warp][nn * WSP + m4 * 4]) = w;
        }
        __syncwarp();

        // ---- rank-32 update: acc[n][d] += ws[n][m] * xs[m][d] (f32x2) ----
#pragma unroll
        for (int m4 = 0; m4 < 8; ++m4) {
            float4 wr[8];
#pragma unroll
            for (int r = 0; r < 8; ++r)
                wr[r] = *reinterpret_cast<const float4*>(
                    &ws[warp][(rg + 4 * r) * WSP + m4 * 4]);
#pragma unroll
            for (int mm = 0; mm < 4; ++mm) {
                const float* xrow = &xs[warp][(m4 * 4 + mm) * D_ + cg * 4];
                ulonglong2 xa = *reinterpret_cast<const ulonglong2*>(xrow);
                ulonglong2 xc = *reinterpret_cast<const ulonglong2*>(xrow + 32);
#pragma unroll
                for (int r = 0; r < 8; ++r) {
                    float wv = (mm == 0) ? wr[r].x
                             : (mm == 1) ? wr[r].y
                             : (mm == 2) ? wr[r].z : wr[r].w;
                    unsigned long long wp = pack2(wv);
                    fma2(acc[r][0], wp, xa.x);
                    fma2(acc[r][1], wp, xa.y);
                    fma2(acc[r][2], wp, xc.x);
                    fma2(acc[r][3], wp, xc.y);
                }
            }
        }
        __syncwarp();  // all lanes done reading smem before next tile overwrites it
    }

    // ---- cross-warp reduction: each warp dumps its 32x64 partial into xs[warp] ----
    __syncthreads();
#pragma unroll
    for (int r = 0; r < 8; ++r) {
        int nn = rg + 4 * r;
        float2 a0 = unpack2(acc[r][0]), a1 = unpack2(acc[r][1]);
        float2 a2 = unpack2(acc[r][2]), a3 = unpack2(acc[r][3]);
        *reinterpret_cast<float4*>(&xs[warp][nn * D_ + cg * 4]) =
            make_float4(a0.x, a0.y, a1.x, a1.y);
        *reinterpret_cast<float4*>(&xs[warp][nn * D_ + cg * 4 + 32]) =
            make_float4(a2.x, a2.y, a3.x, a3.y);
    }
    __syncthreads();

    float* ob = out + ((size_t)b * N_ + n0) * D_;
#pragma unroll
    for (int i = 0; i < 8; ++i) {
        int f4  = threadIdx.x + (NWARP * 32) * i;  // 0..511
        int off = f4 * 4;                          // float offset within tile (0..2047)
        float4 s0 = *reinterpret_cast<const float4*>(&xs[0][off]);
        float4 s1 = *reinterpret_cast<const float4*>(&xs[1][off]);
        float4 o;
        o.x = (s0.x + s1.x) * INV_S;
        o.y = (s0.y + s1.y) * INV_S;
        o.z = (s0.z + s1.z) * INV_S;
        o.w = (s0.w + s1.w) * INV_S;
        *reinterpret_cast<float4*>(ob + off) = o;
    }
}

}  // namespace

extern "C" void kernel_launch(void* const* d_in, const int* in_sizes, int n_in,
                              void* d_out, int out_size) {
    (void)in_sizes; (void)n_in; (void)out_size;
    const float* x  = (const float*)d_in[0];   // [B, N, D] fp32
    const float* gr = (const float*)d_in[1];   // [B, K, N, N] fp32
    float* out = (float*)d_out;                // [B, N, D] fp32

    dim3 grid(N_ / TILE_N, B_);                // (32, 8) = 256 blocks
    fused_gpe_kernel<<<grid, NWARP * 32>>>(x, gr, out);
}

// round 4
// speedup vs baseline: 1.8840x; 1.8840x over previous
#include <cuda_runtime.h>
#include <cstdint>
#include <cstddef>

namespace {

constexpr int B_ = 8;
constexpr int K_ = 9;
constexpr int N_ = 1024;
constexpr int D_ = 64;

constexpr int TILE_N = 32;      // rows per item / group
constexpr int TM     = 32;      // m-tile width per item
constexpr int NWARP  = 2;       // warps per block; warps split the 32 rows (16 each)
constexpr int WSP    = TM + 4;  // padded ws row stride
constexpr int OCC    = 6;       // blocks per SM (forced via launch_bounds)
constexpr int NSM    = 148;     // sm_100a B200
constexpr int N_ITEMS = B_ * (N_ / TILE_N) * (N_ / TM);   // 8192
constexpr int ITEMS_PER_GROUP = N_ / TM;                  // 32

// coefficients (1-eps)^k, eps = 0.01
#define C1 0.99f
#define C2 0.9801f
#define C3 0.970299f
#define C4 0.96059601f
#define C5 0.9509900499f
#define C6 0.941480149401f
#define C7 0.93206534790699f
#define C8 0.9227446944279201f
constexpr float INV_S = 1.0f / 8.648275251635911f;  // 1 / sum_k (0.99)^k

__device__ __forceinline__ unsigned long long pack2(float a) {
    unsigned long long r;
    unsigned int u = __float_as_uint(a);
    asm("mov.b64 %0, {%1, %1};" : "=l"(r) : "r"(u));
    return r;
}
__device__ __forceinline__ void fma2(unsigned long long& d, unsigned long long a,
                                     unsigned long long b) {
    asm("fma.rn.f32x2 %0, %1, %2, %0;" : "+l"(d) : "l"(a), "l"(b));
}
__device__ __forceinline__ float2 unpack2(unsigned long long v) {
    unsigned int lo, hi;
    asm("mov.b64 {%0, %1}, %2;" : "=r"(lo), "=r"(hi) : "l"(v));
    return make_float2(__uint_as_float(lo), __uint_as_float(hi));
}

__device__ __forceinline__ void flush_acc(float* __restrict__ out, int group,
                                          int warp, int rg, int cg,
                                          unsigned long long (&acc)[4][4]) {
    const int pb  = group >> 5;
    const int pn0 = (group & 31) * TILE_N;
    float* ob = out + ((size_t)pb * N_ + pn0 + 16 * warp) * D_;
#pragma unroll
    for (int r = 0; r < 4; ++r) {
        const int row = rg + 4 * r;
        float* o0 = ob + row * D_ + cg * 4;
        float2 a0 = unpack2(acc[r][0]), a1 = unpack2(acc[r][1]);
        float2 a2 = unpack2(acc[r][2]), a3 = unpack2(acc[r][3]);
        atomicAdd(o0 + 0, a0.x * INV_S);
        atomicAdd(o0 + 1, a0.y * INV_S);
        atomicAdd(o0 + 2, a1.x * INV_S);
        atomicAdd(o0 + 3, a1.y * INV_S);
        atomicAdd(o0 + 32, a2.x * INV_S);
        atomicAdd(o0 + 33, a2.y * INV_S);
        atomicAdd(o0 + 34, a3.x * INV_S);
        atomicAdd(o0 + 35, a3.y * INV_S);
    }
}

__global__ __launch_bounds__(NWARP * 32, OCC)
void fused_gpe_kernel(const float* __restrict__ x,
                      const float* __restrict__ gr,
                      float* __restrict__ out) {
    __shared__ float xs[TM * D_];                 // 8 KB   x tile (shared by both warps)
    __shared__ float ws[NWARP][16 * WSP];         // 4.5 KB weighted-kernel tiles (warp-private)

    const int warp = threadIdx.x >> 5;
    const int lane = threadIdx.x & 31;
    const int rg   = lane >> 3;   // 0..3  row group  (local rows = rg + 4*r, r=0..3)
    const int cg   = lane & 7;    // 0..7  col group  (cols cg*4..+3 and cg*4+32..+3)

    // balanced contiguous item range for this block
    const int s = (int)(((long long)blockIdx.x * N_ITEMS) / gridDim.x);
    const int e = (int)(((long long)(blockIdx.x + 1) * N_ITEMS) / gridDim.x);

    // per-warp accumulators: 4 local rows x 8 cols (as f32x2) each lane
    unsigned long long acc[4][4];
#pragma unroll
    for (int r = 0; r < 4; ++r)
#pragma unroll
        for (int i = 0; i < 4; ++i) acc[r][i] = 0ull;

    int cur_group = -1;

    for (int it = s; it < e; ++it) {
        const int group = it >> 5;              // (b, n-group)
        const int mt    = it & (ITEMS_PER_GROUP - 1);
        const int b     = group >> 5;
        const int gn0   = (group & 31) * TILE_N;   // global first row of group
        const int m0    = mt * TM;

        if (group != cur_group) {
            if (cur_group >= 0) {
                flush_acc(out, cur_group, warp, rg, cg, acc);
#pragma unroll
                for (int r = 0; r < 4; ++r)
#pragma unroll
                    for (int i = 0; i < 4; ++i) acc[r][i] = 0ull;
            }
            cur_group = group;
        }

        const float* xb  = x  + (size_t)b * N_ * D_;
        const float* grb = gr + (size_t)b * K_ * N_ * N_;

        __syncthreads();   // previous item's compute done before xs overwrite

        // ---- stage x[m0:m0+32, 0:64] into smem (both warps cooperate) ----
#pragma unroll
        for (int i = 0; i < 8; ++i) {
            int f4 = threadIdx.x + 64 * i;     // 0..511 float4 index
            int m  = f4 >> 4, d4 = f4 & 15;
            *reinterpret_cast<float4*>(&xs[m * D_ + d4 * 4]) =
                *reinterpret_cast<const float4*>(xb + (size_t)(m0 + m) * D_ + d4 * 4);
        }

        // ---- weighted k-sum into ws (warp-private: warp w owns rows 16w..16w+15) ----
#pragma unroll 1
        for (int j = 0; j < 4; ++j) {
            int f4 = lane + 32 * j;            // 0..127
            int nn = f4 >> 3, m4 = f4 & 7;     // nn: local row 0..15, m4: 0..7
            const float* g = grb + (size_t)(gn0 + 16 * warp + nn) * N_ + (m0 + m4 * 4);
            const size_t ks = (size_t)N_ * N_;
            float4 g0 = *reinterpret_cast<const float4*>(g);
            float4 g1 = *reinterpret_cast<const float4*>(g + ks);
            float4 g2 = *reinterpret_cast<const float4*>(g + 2 * ks);
            float4 g3 = *reinterpret_cast<const float4*>(g + 3 * ks);
            float4 g4 = *reinterpret_cast<const float4*>(g + 4 * ks);
            float4 g5 = *reinterpret_cast<const float4*>(g + 5 * ks);
            float4 g6 = *reinterpret_cast<const float4*>(g + 6 * ks);
            float4 g7 = *reinterpret_cast<const float4*>(g + 7 * ks);
            float4 g8 = *reinterpret_cast<const float4*>(g + 8 * ks);
            float4 w;
            w.x = g0.x; w.y = g0.y; w.z = g0.z; w.w = g0.w;
            w.x = fmaf(g1.x, C1, w.x); w.y = fmaf(g1.y, C1, w.y); w.z = fmaf(g1.z, C1, w.z); w.w = fmaf(g1.w, C1, w.w);
            w.x = fmaf(g2.x, C2, w.x); w.y = fmaf(g2.y, C2, w.y); w.z = fmaf(g2.z, C2, w.z); w.w = fmaf(g2.w, C2, w.w);
            w.x = fmaf(g3.x, C3, w.x); w.y = fmaf(g3.y, C3, w.y); w.z = fmaf(g3.z, C3, w.z); w.w = fmaf(g3.w, C3, w.w);
            w.x = fmaf(g4.x, C4, w.x); w.y = fmaf(g4.y, C4, w.y); w.z = fmaf(g4.z, C4, w.z); w.w = fmaf(g4.w, C4, w.w);
            w.x = fmaf(g5.x, C5, w.x); w.y = fmaf(g5.y, C5, w.y); w.z = fmaf(g5.z, C5, w.z); w.w = fmaf(g5.w, C5, w.w);
            w.x = fmaf(g6.x, C6, w.x); w.y = fmaf(g6.y, C6, w.y); w.z = fmaf(g6.z, C6, w.z); w.w = fmaf(g6.w, C6, w.w);
            w.x = fmaf(g7.x, C7, w.x); w.y = fmaf(g7.y, C7, w.y); w.z = fmaf(g7.z, C7, w.z); w.w = fmaf(g7.w, C7, w.w);
            w.x = fmaf(g8.x, C8, w.x); w.y = fmaf(g8.y, C8, w.y); w.z = fmaf(g8.z, C8, w.z); w.w = fmaf(g8.w, C8, w.w);
            *reinterpret_cast<float4*>(&ws[warp][nn * WSP + m4 * 4]) = w;
        }
        __syncwarp();      // ws ready for this warp
        __syncthreads();   // xs ready (both warps' stores done)

        // ---- rank-32 update: acc[r][*] += ws[row][m] * xs[m][*] ----
#pragma unroll
        for (int m4 = 0; m4 < 8; ++m4) {
            float4 wr[4];
#pragma unroll
            for (int r = 0; r < 4; ++r)
                wr[r] = *reinterpret_cast<const float4*>(
                    &ws[warp][(rg + 4 * r) * WSP + m4 * 4]);
#pragma unroll
            for (int mm = 0; mm < 4; ++mm) {
                const float* xrow = &xs[(m4 * 4 + mm) * D_ + cg * 4];
                ulonglong2 xa = *reinterpret_cast<const ulonglong2*>(xrow);
                ulonglong2 xc = *reinterpret_cast<const ulonglong2*>(xrow + 32);
#pragma unroll
                for (int r = 0; r < 4; ++r) {
                    float wv = (mm == 0) ? wr[r].x
                             : (mm == 1) ? wr[r].y
                             : (mm == 2) ? wr[r].z : wr[r].w;
                    unsigned long long wp = pack2(wv);
                    fma2(acc[r][0], wp, xa.x);
                    fma2(acc[r][1], wp, xa.y);
                    fma2(acc[r][2], wp, xc.x);
                    fma2(acc[r][3], wp, xc.y);
                }
            }
        }
    }

    // final flush
    if (cur_group >= 0)
        flush_acc(out, cur_group, warp, rg, cg, acc);
}

}  // namespace

extern "C" void kernel_launch(void* const* d_in, const int* in_sizes, int n_in,
                              void* d_out, int out_size) {
    (void)in_sizes; (void)n_in;
    const float* x  = (const float*)d_in[0];   // [B, N, D] fp32
    const float* gr = (const float*)d_in[1];   // [B, K, N, N] fp32
    float* out = (float*)d_out;                // [B, N, D] fp32

    int grid = NSM * OCC;                      // 888: one full resident wave
    if (grid > N_ITEMS) grid = N_ITEMS;

    cudaMemsetAsync(d_out, 0, (size_t)out_size * sizeof(float), 0);
    fused_gpe_kernel<<<grid, NWARP * 32>>>(x, gr, out);
}

// round 5
// speedup vs baseline: 2.1250x; 1.1279x over previous
#include <cuda_runtime.h>
#include <cstdint>
#include <cstddef>

namespace {

constexpr int B_ = 8;
constexpr int K_ = 9;
constexpr int N_ = 1024;
constexpr int D_ = 64;

constexpr int TILE_N = 32;      // rows per item / group
constexpr int TM     = 32;      // m-tile width per item
constexpr int NWARP  = 2;       // warps per block; warps split the 32 rows (16 each)
constexpr int WSP    = TM + 4;  // padded ws row stride
constexpr int OCC    = 6;       // blocks per SM
constexpr int NSM    = 148;     // sm_100a B200
constexpr int N_ITEMS = B_ * (N_ / TILE_N) * (N_ / TM);   // 8192
constexpr int ITEMS_PER_GROUP = N_ / TM;                  // 32

// coefficients (1-eps)^k, eps = 0.01
__device__ __constant__ const float CK[9] = {
    1.0f, 0.99f, 0.9801f, 0.970299f, 0.96059601f, 0.9509900499f,
    0.941480149401f, 0.93206534790699f, 0.9227446944279201f};
#define C1 0.99f
#define C2 0.9801f
#define C3 0.970299f
#define C4 0.96059601f
#define C5 0.9509900499f
#define C6 0.941480149401f
#define C7 0.93206534790699f
#define C8 0.9227446944279201f
constexpr float INV_S = 1.0f / 8.648275251635911f;  // 1 / sum_k (0.99)^k

__device__ __forceinline__ unsigned long long pack2(float a) {
    unsigned long long r;
    unsigned int u = __float_as_uint(a);
    asm("mov.b64 %0, {%1, %1};" : "=l"(r) : "r"(u));
    return r;
}
__device__ __forceinline__ void fma2(unsigned long long& d, unsigned long long a,
                                     unsigned long long b) {
    asm("fma.rn.f32x2 %0, %1, %2, %0;" : "+l"(d) : "l"(a), "l"(b));
}
__device__ __forceinline__ float2 unpack2(unsigned long long v) {
    unsigned int lo, hi;
    asm("mov.b64 {%0, %1}, %2;" : "=r"(lo), "=r"(hi) : "l"(v));
    return make_float2(__uint_as_float(lo), __uint_as_float(hi));
}

// weighted k-sum of 9 float4s with immediate coefficients
__device__ __forceinline__ float4 wsum9(const float4 (&g)[9]) {
    float4 w = g[0];
    w.x = fmaf(g[1].x, C1, w.x); w.y = fmaf(g[1].y, C1, w.y); w.z = fmaf(g[1].z, C1, w.z); w.w = fmaf(g[1].w, C1, w.w);
    w.x = fmaf(g[2].x, C2, w.x); w.y = fmaf(g[2].y, C2, w.y); w.z = fmaf(g[2].z, C2, w.z); w.w = fmaf(g[2].w, C2, w.w);
    w.x = fmaf(g[3].x, C3, w.x); w.y = fmaf(g[3].y, C3, w.y); w.z = fmaf(g[3].z, C3, w.z); w.w = fmaf(g[3].w, C3, w.w);
    w.x = fmaf(g[4].x, C4, w.x); w.y = fmaf(g[4].y, C4, w.y); w.z = fmaf(g[4].z, C4, w.z); w.w = fmaf(g[4].w, C4, w.w);
    w.x = fmaf(g[5].x, C5, w.x); w.y = fmaf(g[5].y, C5, w.y); w.z = fmaf(g[5].z, C5, w.z); w.w = fmaf(g[5].w, C5, w.w);
    w.x = fmaf(g[6].x, C6, w.x); w.y = fmaf(g[6].y, C6, w.y); w.z = fmaf(g[6].z, C6, w.z); w.w = fmaf(g[6].w, C6, w.w);
    w.x = fmaf(g[7].x, C7, w.x); w.y = fmaf(g[7].y, C7, w.y); w.z = fmaf(g[7].z, C7, w.z); w.w = fmaf(g[7].w, C7, w.w);
    w.x = fmaf(g[8].x, C8, w.x); w.y = fmaf(g[8].y, C8, w.y); w.z = fmaf(g[8].z, C8, w.z); w.w = fmaf(g[8].w, C8, w.w);
    return w;
}

__device__ __forceinline__ void flush_acc(float* __restrict__ out, int group,
                                          int warp, int rg, int cg,
                                          unsigned long long (&acc)[4][4]) {
    const int pb  = group >> 5;
    const int pn0 = (group & 31) * TILE_N;
    float* ob = out + ((size_t)pb * N_ + pn0 + 16 * warp) * D_;
#pragma unroll
    for (int r = 0; r < 4; ++r) {
        const int row = rg + 4 * r;
        float* o0 = ob + row * D_ + cg * 4;
        float2 a0 = unpack2(acc[r][0]), a1 = unpack2(acc[r][1]);
        float2 a2 = unpack2(acc[r][2]), a3 = unpack2(acc[r][3]);
        atomicAdd(o0 + 0, a0.x * INV_S);
        atomicAdd(o0 + 1, a0.y * INV_S);
        atomicAdd(o0 + 2, a1.x * INV_S);
        atomicAdd(o0 + 3, a1.y * INV_S);
        atomicAdd(o0 + 32, a2.x * INV_S);
        atomicAdd(o0 + 33, a2.y * INV_S);
        atomicAdd(o0 + 34, a3.x * INV_S);
        atomicAdd(o0 + 35, a3.y * INV_S);
    }
}

__global__ __launch_bounds__(NWARP * 32, OCC)
void fused_gpe_kernel(const float* __restrict__ x,
                      const float* __restrict__ gr,
                      float* __restrict__ out) {
    __shared__ float xs[TM * D_];                 // 8 KB   x tile (shared by both warps)
    __shared__ float ws[NWARP][16 * WSP];         // 4.5 KB weighted-kernel tiles (warp-private)

    const int warp = threadIdx.x >> 5;
    const int lane = threadIdx.x & 31;
    const int rg   = lane >> 3;   // 0..3  row group  (local rows = rg + 4*r, r=0..3)
    const int cg   = lane & 7;    // 0..7  col group  (cols cg*4..+3 and cg*4+32..+3)

    // balanced contiguous item range for this block
    const int s = (int)(((long long)blockIdx.x * N_ITEMS) / gridDim.x);
    const int e = (int)(((long long)(blockIdx.x + 1) * N_ITEMS) / gridDim.x);

    unsigned long long acc[4][4];
#pragma unroll
    for (int r = 0; r < 4; ++r)
#pragma unroll
        for (int i = 0; i < 4; ++i) acc[r][i] = 0ull;

    int cur_group = -1;

    for (int it = s; it < e; ++it) {
        const int group = it >> 5;              // (b, n-group)
        const int mt    = it & (ITEMS_PER_GROUP - 1);
        const int b     = group >> 5;
        const int gn0   = (group & 31) * TILE_N;
        const int m0    = mt * TM;

        if (group != cur_group) {
            if (cur_group >= 0) {
                flush_acc(out, cur_group, warp, rg, cg, acc);
#pragma unroll
                for (int r = 0; r < 4; ++r)
#pragma unroll
                    for (int i = 0; i < 4; ++i) acc[r][i] = 0ull;
            }
            cur_group = group;
        }

        const float* xb  = x  + (size_t)b * N_ * D_;
        const float* grb = gr + (size_t)b * K_ * N_ * N_;

        __syncthreads();   // previous item's compute done before xs overwrite

        // ---- stage x[m0:m0+32, 0:64] into smem (both warps cooperate) ----
#pragma unroll
        for (int i = 0; i < 8; ++i) {
            int f4 = threadIdx.x + 64 * i;     // 0..511 float4 index
            int m  = f4 >> 4, d4 = f4 & 15;
            *reinterpret_cast<float4*>(&xs[m * D_ + d4 * 4]) =
                *reinterpret_cast<const float4*>(xb + (size_t)(m0 + m) * D_ + d4 * 4);
        }

        // ---- weighted k-sum into ws; 2x-unrolled: 18 LDG.128 batched per step ----
        const size_t ks = (size_t)N_ * N_;
#pragma unroll 1
        for (int j = 0; j < 4; j += 2) {
            const int f4a = lane + 32 * j;
            const int f4b = lane + 32 * (j + 1);
            const int nna = f4a >> 3, m4a = f4a & 7;
            const int nnb = f4b >> 3, m4b = f4b & 7;
            const float* pa = grb + (size_t)(gn0 + 16 * warp + nna) * N_ + (m0 + m4a * 4);
            const float* pb = grb + (size_t)(gn0 + 16 * warp + nnb) * N_ + (m0 + m4b * 4);
            float4 ga[9], gb[9];
#pragma unroll
            for (int k = 0; k < 9; ++k)
                ga[k] = *reinterpret_cast<const float4*>(pa + k * ks);
#pragma unroll
            for (int k = 0; k < 9; ++k)
                gb[k] = *reinterpret_cast<const float4*>(pb + k * ks);
            float4 wa = wsum9(ga);
            float4 wb = wsum9(gb);
            *reinterpret_cast<float4*>(&ws[warp][nna * WSP + m4a * 4]) = wa;
            *reinterpret_cast<float4*>(&ws[warp][nnb * WSP + m4b * 4]) = wb;
        }
        __syncwarp();      // ws ready for this warp
        __syncthreads();   // xs ready (both warps' stores done)

        // ---- rank-32 update: acc[r][*] += ws[row][m] * xs[m][*] ----
#pragma unroll
        for (int m4 = 0; m4 < 8; ++m4) {
            float4 wr[4];
#pragma unroll
            for (int r = 0; r < 4; ++r)
                wr[r] = *reinterpret_cast<const float4*>(
                    &ws[warp][(rg + 4 * r) * WSP + m4 * 4]);
#pragma unroll
            for (int mm = 0; mm < 4; ++mm) {
                const float* xrow = &xs[(m4 * 4 + mm) * D_ + cg * 4];
                ulonglong2 xa = *reinterpret_cast<const ulonglong2*>(xrow);
                ulonglong2 xc = *reinterpret_cast<const ulonglong2*>(xrow + 32);
#pragma unroll
                for (int r = 0; r < 4; ++r) {
                    float wv = (mm == 0) ? wr[r].x
                             : (mm == 1) ? wr[r].y
                             : (mm == 2) ? wr[r].z : wr[r].w;
                    unsigned long long wp = pack2(wv);
                    fma2(acc[r][0], wp, xa.x);
                    fma2(acc[r][1], wp, xa.y);
                    fma2(acc[r][2], wp, xc.x);
                    fma2(acc[r][3], wp, xc.y);
                }
            }
        }
    }

    // final flush
    if (cur_group >= 0)
        flush_acc(out, cur_group, warp, rg, cg, acc);
}

}  // namespace

extern "C" void kernel_launch(void* const* d_in, const int* in_sizes, int n_in,
                              void* d_out, int out_size) {
    (void)in_sizes; (void)n_in;
    const float* x  = (const float*)d_in[0];   // [B, N, D] fp32
    const float* gr = (const float*)d_in[1];   // [B, K, N, N] fp32
    float* out = (float*)d_out;                // [B, N, D] fp32

    int grid = NSM * OCC;                      // 888: one full resident wave
    if (grid > N_ITEMS) grid = N_ITEMS;

    cudaMemsetAsync(d_out, 0, (size_t)out_size * sizeof(float), 0);
    fused_gpe_kernel<<<grid, NWARP * 32>>>(x, gr, out);
}